// round 15
// baseline (speedup 1.0000x reference)
#include <cuda_runtime.h>
#include <cuda_fp16.h>
#include <math_constants.h>
#include <cstdint>

#define BB 8
#define TT 64
#define NP 196
#define HH 6
#define HD 64
#define CC 384
#define C3 1152
#define BT (BB*TT)           /* 512 */
#define MROWS (BT*NP)        /* 100352 */
#define NBH (BT*HH)          /* 3072 */
#define QK_SCALE 0.125f

#define BK 64
#define NKT 6                /* K = 384, single fp16 pass */
#define STRB 144             /* smem row stride: 64 fp16 + 8 pad */
#define STAGE_BYTES (128*STRB)          /* 18432 */
#define B_REGION (2*STAGE_BYTES)        /* A: 2 stages, then B: 2 stages */
#define SMEM_SZ (4*STAGE_BYTES)         /* 73728 -> 3 CTAs/SM */

/* attention smem: K + V, 208-row regions */
#define KSTRB 144
#define SM_KH 0
#define SM_VH 29952          /* 208*144 */
#define ATT_SMEM 59904

/* merged conv grid split */
#define NBLK_A  (MROWS*96/256)   /* 37632 */
#define NBLK_WQ (C3*96/256)      /* 432 */
#define NBLK_WP (CC*CC/256)      /* 576 */

/* ---------------- scratch ------------------------------------------------- */
__device__ __half g_Qh[(size_t)NBH*NP*HD];     /* [bh][n][d], pre-scaled */
__device__ __half g_Kh[(size_t)NBH*NP*HD];
__device__ __half g_Vh[(size_t)NBH*NP*HD];
__device__ __half g_Xh[(size_t)MROWS*CC];      /* X fp16 */
__device__ __half g_Ah[(size_t)MROWS*CC];      /* attn out fp16 */
__device__ __half g_Wqc[(size_t)C3*CC];        /* Wqkv fp16 */
__device__ __half g_Wpc[(size_t)CC*CC];        /* Wproj permuted fp16 */

/* ---------------- PTX helpers --------------------------------------------- */
__device__ __forceinline__ uint32_t smem_u32(const void* p) {
    uint32_t a;
    asm("{ .reg .u64 t; cvta.to.shared.u64 t, %1; cvt.u32.u64 %0, t; }" : "=r"(a) : "l"(p));
    return a;
}
__device__ __forceinline__ void cpasync16(uint32_t s, const void* g) {
    asm volatile("cp.async.cg.shared.global [%0], [%1], 16;" :: "r"(s), "l"(g));
}
#define CP_COMMIT() asm volatile("cp.async.commit_group;" ::: "memory")
#define CP_WAIT1()  asm volatile("cp.async.wait_group 1;" ::: "memory")
#define CP_WAIT0()  asm volatile("cp.async.wait_group 0;" ::: "memory")

__device__ __forceinline__ void ldsm_x4(uint32_t* r, uint32_t addr) {
    asm volatile("ldmatrix.sync.aligned.m8n8.x4.shared.b16 {%0,%1,%2,%3}, [%4];"
                 : "=r"(r[0]), "=r"(r[1]), "=r"(r[2]), "=r"(r[3]) : "r"(addr));
}
__device__ __forceinline__ void ldsm_x4_t(uint32_t* r, uint32_t addr) {
    asm volatile("ldmatrix.sync.aligned.m8n8.x4.trans.shared.b16 {%0,%1,%2,%3}, [%4];"
                 : "=r"(r[0]), "=r"(r[1]), "=r"(r[2]), "=r"(r[3]) : "r"(addr));
}
__device__ __forceinline__ void mma16816(float* c, const uint32_t* a, const uint32_t* b) {
    asm volatile("mma.sync.aligned.m16n8k16.row.col.f32.f16.f16.f32 "
                 "{%0,%1,%2,%3}, {%4,%5,%6,%7}, {%8,%9}, {%0,%1,%2,%3};"
                 : "+f"(c[0]), "+f"(c[1]), "+f"(c[2]), "+f"(c[3])
                 : "r"(a[0]), "r"(a[1]), "r"(a[2]), "r"(a[3]), "r"(b[0]), "r"(b[1]));
}
__device__ __forceinline__ uint32_t pk2h(__half a, __half b) {
    __half2 t; t.x = a; t.y = b;
    return *(uint32_t*)&t;
}

/* ---------------- merged conversions --------------------------------------- */
__global__ __launch_bounds__(256) void conv_all(const float* __restrict__ x,
                                                const float* __restrict__ Wq,
                                                const float* __restrict__ Wp) {
    int b = blockIdx.x;
    if (b < NBLK_A) {
        int t = b * 256 + threadIdx.x;
        float4 v = *(const float4*)(x + (size_t)t * 4);
        uint2 uh;
        uh.x = pk2h(__float2half_rn(v.x), __float2half_rn(v.y));
        uh.y = pk2h(__float2half_rn(v.z), __float2half_rn(v.w));
        *(uint2*)(g_Xh + (size_t)t * 4) = uh;
    } else if (b < NBLK_A + NBLK_WQ) {
        int t = (b - NBLK_A) * 256 + threadIdx.x;
        float4 v = *(const float4*)(Wq + (size_t)t * 4);
        uint2 uh;
        uh.x = pk2h(__float2half_rn(v.x), __float2half_rn(v.y));
        uh.y = pk2h(__float2half_rn(v.z), __float2half_rn(v.w));
        *(uint2*)(g_Wqc + (size_t)t * 4) = uh;
    } else {
        int t = (b - NBLK_A - NBLK_WQ) * 256 + threadIdx.x;
        int o = t / CC, c = t - o * CC;
        int h = c >> 6, d = c & 63;
        g_Wpc[(size_t)o * CC + c] = __float2half_rn(Wp[(size_t)o * CC + d * HH + h]);
    }
}

/* ---------------- mma.sync GEMM mainloop ------------------------------------ */
/* CTA 128x128, 4 warps (2x2), warp tile 64x64. fp16, BK=64, 2-stage, K=384.  */
__device__ __forceinline__ void prefetch_kt(const __half* Ab, const __half* Bb,
                                            uint32_t sm, int kt, int tid) {
    const int st = kt & 1;
    const int k0 = kt * 64;
    const uint32_t sa = sm + st * STAGE_BYTES;
    const uint32_t sb = sm + B_REGION + st * STAGE_BYTES;
    #pragma unroll
    for (int it = 0; it < 8; it++) {
        int idx = it * 128 + tid;
        int r = idx >> 3, jj = idx & 7;
        cpasync16(sa + r * STRB + jj * 16, Ab + (size_t)r * CC + k0 + jj * 8);
        cpasync16(sb + r * STRB + jj * 16, Bb + (size_t)r * CC + k0 + jj * 8);
    }
}
__device__ __forceinline__ void gemm_mainloop(const __half* __restrict__ A,
                                              const __half* __restrict__ Bm,
                                              int rowBase, int colBase,
                                              uint32_t sm, float acc[4][8][4]) {
    const int tid  = threadIdx.x;
    const int wid  = tid >> 5, lane = tid & 31;
    const int wr   = wid >> 1, wc = wid & 1;

    #pragma unroll
    for (int i = 0; i < 4; i++)
        #pragma unroll
        for (int j = 0; j < 8; j++)
            #pragma unroll
            for (int k = 0; k < 4; k++) acc[i][j][k] = 0.f;

    const __half* Ab = A + (size_t)rowBase * CC;
    const __half* Bb = Bm + (size_t)colBase * CC;

    prefetch_kt(Ab, Bb, sm, 0, tid); CP_COMMIT();

    const uint32_t aoff = (uint32_t)((wr * 64 + (lane & 15)) * STRB + ((lane >> 4) & 1) * 16);
    const uint32_t boff = (uint32_t)((wc * 64 + (lane & 7) + ((lane >> 4) & 1) * 8) * STRB
                                     + ((lane >> 3) & 1) * 16);

    #pragma unroll 1
    for (int kt = 0; kt < NKT; kt++) {
        if (kt + 1 < NKT) { prefetch_kt(Ab, Bb, sm, kt + 1, tid); }
        CP_COMMIT();
        CP_WAIT1();
        __syncthreads();

        const int st = kt & 1;
        const uint32_t aBase = sm + st * STAGE_BYTES + aoff;
        const uint32_t bBase = sm + B_REGION + st * STAGE_BYTES + boff;
        #pragma unroll
        for (int ks = 0; ks < 4; ks++) {
            uint32_t af[4][4], bf[4][4];
            #pragma unroll
            for (int jj = 0; jj < 4; jj++)
                ldsm_x4(bf[jj], bBase + (uint32_t)(jj * 16 * STRB + ks * 32));
            #pragma unroll
            for (int i = 0; i < 4; i++)
                ldsm_x4(af[i], aBase + (uint32_t)(i * 16 * STRB + ks * 32));
            #pragma unroll
            for (int i = 0; i < 4; i++)
                #pragma unroll
                for (int jj = 0; jj < 4; jj++) {
                    mma16816(acc[i][2 * jj],     af[i], bf[jj]);
                    mma16816(acc[i][2 * jj + 1], af[i], bf[jj] + 2);
                }
        }
        __syncthreads();
    }
    CP_WAIT0();
}

/* ---------------- QKV GEMM kernel (direct-STG epilogue) -------------------- */
__global__ __launch_bounds__(128, 3) void qkv_mma(const float* __restrict__ bias) {
    extern __shared__ char dynsm[];
    uint32_t sm = smem_u32(dynsm);
    const int colBase = blockIdx.x * 128;
    const int rowBase = blockIdx.y * 128;
    const int s = colBase / CC;

    float acc[4][8][4];
    gemm_mainloop(g_Xh, g_Wqc, rowBase, colBase, sm, acc);

    const int tid = threadIdx.x, wid = tid >> 5, lane = tid & 31;
    const int wr = wid >> 1, wc = wid & 1;
    const int rl = lane >> 2, cl = 2 * (lane & 3);
    const int hb = (colBase - s * CC) >> 6;
    const float mul = (s == 0) ? QK_SCALE : 1.0f;
    __half* dst = (s == 0) ? g_Qh : (s == 1) ? g_Kh : g_Vh;

    #pragma unroll
    for (int i = 0; i < 4; i++) {
        int m0 = rowBase + wr * 64 + i * 16 + rl;
        int m1 = m0 + 8;
        int bt0 = m0 / NP, n0 = m0 - bt0 * NP;
        int bt1 = m1 / NP, n1 = m1 - bt1 * NP;
        #pragma unroll
        for (int j = 0; j < 8; j++) {
            int c = wc * 64 + j * 8 + cl;
            int hh = c >> 6, d = c & 63;
            float2 bj = *(const float2*)(bias + colBase + c);
            float v0 = (acc[i][j][0] + bj.x) * mul;
            float v1 = (acc[i][j][1] + bj.y) * mul;
            float v2 = (acc[i][j][2] + bj.x) * mul;
            float v3 = (acc[i][j][3] + bj.y) * mul;
            size_t o0 = ((size_t)(bt0 * HH + hb + hh) * NP + n0) * HD + d;
            size_t o1 = ((size_t)(bt1 * HH + hb + hh) * NP + n1) * HD + d;
            *(uint32_t*)(dst + o0) = pk2h(__float2half_rn(v0), __float2half_rn(v1));
            *(uint32_t*)(dst + o1) = pk2h(__float2half_rn(v2), __float2half_rn(v3));
        }
    }
}

/* ---------------- proj GEMM kernel (direct-STG epilogue) ------------------- */
__global__ __launch_bounds__(128, 3) void proj_mma(const float* __restrict__ bias,
                                                   float* __restrict__ out) {
    extern __shared__ char dynsm[];
    uint32_t sm = smem_u32(dynsm);
    const int colBase = blockIdx.x * 128;
    const int rowBase = blockIdx.y * 128;

    float acc[4][8][4];
    gemm_mainloop(g_Ah, g_Wpc, rowBase, colBase, sm, acc);

    const int tid = threadIdx.x, wid = tid >> 5, lane = tid & 31;
    const int wr = wid >> 1, wc = wid & 1;
    const int rl = lane >> 2, cl = 2 * (lane & 3);

    #pragma unroll
    for (int i = 0; i < 4; i++) {
        int m0 = rowBase + wr * 64 + i * 16 + rl;
        int m1 = m0 + 8;
        #pragma unroll
        for (int j = 0; j < 8; j++) {
            int col = colBase + wc * 64 + j * 8 + cl;
            float2 bj = *(const float2*)(bias + col);
            float2 v0; v0.x = acc[i][j][0] + bj.x; v0.y = acc[i][j][1] + bj.y;
            float2 v1; v1.x = acc[i][j][2] + bj.x; v1.y = acc[i][j][3] + bj.y;
            *(float2*)(out + (size_t)m0 * CC + col) = v0;
            *(float2*)(out + (size_t)m1 * CC + col) = v1;
        }
    }
}

/* ---------------- attention via mma.sync (pure fp16, x4 LDSM) -------------- */
template<int NT>
__device__ __forceinline__ void attn_chunk(uint32_t sb, int lane, int cbase,
                                           const uint32_t qh[4][4],
                                           float o[8][4], float& lp0, float& lp1) {
    float s[NT][4];
    #pragma unroll
    for (int t = 0; t < NT; t++)
        #pragma unroll
        for (int e = 0; e < 4; e++) s[t][e] = 0.f;

    /* --- QK: x4 loads two n-tiles (lanes 0-15: rows, 16-31: k-hi half) --- */
    #pragma unroll
    for (int tp = 0; tp < NT / 2; tp++) {
        #pragma unroll
        for (int ks = 0; ks < 4; ks++) {
            uint32_t r[4];
            uint32_t off = (uint32_t)((cbase + tp * 16 + (lane & 15)) * KSTRB
                                      + ks * 32 + ((lane >> 4) & 1) * 16);
            ldsm_x4(r, sb + SM_KH + off);
            uint32_t b0[2] = { r[0], r[2] };
            uint32_t b1[2] = { r[1], r[3] };
            mma16816(s[2 * tp],     qh[ks], b0);
            mma16816(s[2 * tp + 1], qh[ks], b1);
        }
    }

    /* --- exp + mask + pack P --- */
    uint32_t phi[NT/2][4];
    #pragma unroll
    for (int t = 0; t < NT; t++) {
        int c0 = cbase + t * 8 + 2 * (lane & 3);
        float p0 = (c0     < NP) ? __expf(s[t][0]) : 0.f;
        float p1 = (c0 + 1 < NP) ? __expf(s[t][1]) : 0.f;
        float p2 = (c0     < NP) ? __expf(s[t][2]) : 0.f;
        float p3 = (c0 + 1 < NP) ? __expf(s[t][3]) : 0.f;
        lp0 += p0 + p1;
        lp1 += p2 + p3;
        int j = t >> 1, oreg = (t & 1) * 2;
        phi[j][oreg]     = pk2h(__float2half_rn(p0), __float2half_rn(p1));
        phi[j][oreg + 1] = pk2h(__float2half_rn(p2), __float2half_rn(p3));
    }

    /* --- PV: x4.trans loads two nd-groups (lanes 16-31: +16B col group) --- */
    #pragma unroll
    for (int j = 0; j < NT / 2; j++) {
        #pragma unroll
        for (int np = 0; np < 4; np++) {
            uint32_t r[4];
            uint32_t off = (uint32_t)((cbase + j * 16 + (lane & 15)) * KSTRB
                                      + np * 32 + ((lane >> 4) & 1) * 16);
            ldsm_x4_t(r, sb + SM_VH + off);
            mma16816(o[2 * np],     phi[j], r);
            mma16816(o[2 * np + 1], phi[j], r + 2);
        }
    }
}

__global__ __launch_bounds__(416, 1) void attn_mma() {
    extern __shared__ char smc[];
    uint32_t sb = smem_u32(smc);
    const int bx = blockIdx.x;                 /* bt*6 + h */
    const int tid = threadIdx.x, wid = tid >> 5, lane = tid & 31;

    const size_t base = (size_t)bx * NP * HD;
    for (int i = tid; i < NP * 8; i += 416) {
        int r = i >> 3, j = i & 7;
        uint32_t doff = (uint32_t)(r * KSTRB + j * 16);
        cpasync16(sb + SM_KH + doff, (const uint4*)(g_Kh + base) + i);
        cpasync16(sb + SM_VH + doff, (const uint4*)(g_Vh + base) + i);
    }
    CP_COMMIT();
    if (tid < 108)
        *(uint4*)(smc + SM_VH + 196 * KSTRB + tid * 16) = make_uint4(0, 0, 0, 0);

    uint32_t qh[4][4];
    {
        const uint32_t* qhp = (const uint32_t*)(g_Qh + base);
        int r  = wid * 16 + (lane >> 2);
        int r2 = r + 8;
        int ra  = (r  < NP) ? r  : NP - 1;
        int r2a = (r2 < NP) ? r2 : NP - 1;
        int c = lane & 3;
        #pragma unroll
        for (int ks = 0; ks < 4; ks++) {
            qh[ks][0] = qhp[ra  * 32 + ks * 8 + c];
            qh[ks][1] = qhp[r2a * 32 + ks * 8 + c];
            qh[ks][2] = qhp[ra  * 32 + ks * 8 + 4 + c];
            qh[ks][3] = qhp[r2a * 32 + ks * 8 + 4 + c];
        }
    }
    CP_WAIT0();
    __syncthreads();

    float o[8][4];
    #pragma unroll
    for (int nd = 0; nd < 8; nd++)
        #pragma unroll
        for (int e = 0; e < 4; e++) o[nd][e] = 0.f;
    float lp0 = 0.f, lp1 = 0.f;

    attn_chunk<14>(sb, lane, 0,   qh, o, lp0, lp1);
    attn_chunk<12>(sb, lane, 112, qh, o, lp0, lp1);

    lp0 += __shfl_xor_sync(0xFFFFFFFFu, lp0, 1);
    lp0 += __shfl_xor_sync(0xFFFFFFFFu, lp0, 2);
    lp1 += __shfl_xor_sync(0xFFFFFFFFu, lp1, 1);
    lp1 += __shfl_xor_sync(0xFFFFFFFFu, lp1, 2);
    const float inv0 = 1.0f / lp0, inv1 = 1.0f / lp1;

    const int bt = bx / HH, h = bx - bt * HH;
    const int r0 = wid * 16 + (lane >> 2);
    const int cl = 2 * (lane & 3);
    #pragma unroll
    for (int nd = 0; nd < 8; nd++) {
        int col = h * HD + nd * 8 + cl;
        if (r0 < NP) {
            size_t ro = ((size_t)bt * NP + r0) * CC + col;
            *(uint32_t*)(g_Ah + ro) = pk2h(__float2half_rn(o[nd][0] * inv0),
                                           __float2half_rn(o[nd][1] * inv0));
        }
        if (r0 + 8 < NP) {
            size_t ro = ((size_t)bt * NP + r0 + 8) * CC + col;
            *(uint32_t*)(g_Ah + ro) = pk2h(__float2half_rn(o[nd][2] * inv1),
                                           __float2half_rn(o[nd][3] * inv1));
        }
    }
}

/* ---------------- launch --------------------------------------------------- */
extern "C" void kernel_launch(void* const* d_in, const int* in_sizes, int n_in,
                              void* d_out, int out_size) {
    const float* x     = (const float*)d_in[0];
    const float* Wqkv  = (const float*)d_in[1];
    const float* bqkv  = (const float*)d_in[2];
    const float* Wproj = (const float*)d_in[3];
    const float* bproj = (const float*)d_in[4];
    float* out = (float*)d_out;

    cudaFuncSetAttribute(attn_mma, cudaFuncAttributeMaxDynamicSharedMemorySize, ATT_SMEM);
    cudaFuncSetAttribute(qkv_mma,  cudaFuncAttributeMaxDynamicSharedMemorySize, SMEM_SZ);
    cudaFuncSetAttribute(proj_mma, cudaFuncAttributeMaxDynamicSharedMemorySize, SMEM_SZ);

    conv_all<<<NBLK_A + NBLK_WQ + NBLK_WP, 256>>>(x, Wqkv, Wproj);
    qkv_mma<<<dim3(C3 / 128, MROWS / 128), 128, SMEM_SZ>>>(bqkv);
    attn_mma<<<NBH, 416, ATT_SMEM>>>();
    proj_mma<<<dim3(CC / 128, MROWS / 128), 128, SMEM_SZ>>>(bproj, out);
}

// round 16
// speedup vs baseline: 1.0429x; 1.0429x over previous
#include <cuda_runtime.h>
#include <cuda_fp16.h>
#include <math_constants.h>
#include <cstdint>

#define BB 8
#define TT 64
#define NP 196
#define HH 6
#define HD 64
#define CC 384
#define C3 1152
#define BT (BB*TT)           /* 512 */
#define MROWS (BT*NP)        /* 100352 */
#define NBH (BT*HH)          /* 3072 */
#define QK_SCALE 0.125f

#define BK 64
#define NKT 6                /* K = 384, single fp16 pass */
#define STRB 144             /* smem row stride: 64 fp16 + 8 pad */
#define STAGE_BYTES (128*STRB)          /* 18432 */
#define B_REGION (2*STAGE_BYTES)        /* A: 2 stages, then B: 2 stages */
#define SMEM_SZ (4*STAGE_BYTES)         /* 73728 -> 3 CTAs/SM */

/* attention smem: K + V, 208-row regions */
#define KSTRB 144
#define SM_KH 0
#define SM_VH 29952          /* 208*144 */
#define ATT_SMEM 59904

/* merged conv grid split */
#define NBLK_A  (MROWS*96/256)   /* 37632 */
#define NBLK_WQ (C3*96/256)      /* 432 */
#define NBLK_WP (CC*CC/256)      /* 576 */

/* ---------------- scratch ------------------------------------------------- */
__device__ __half g_Qh[(size_t)NBH*NP*HD];     /* [bh][n][d], pre-scaled */
__device__ __half g_Kh[(size_t)NBH*NP*HD];
__device__ __half g_Vh[(size_t)NBH*NP*HD];
__device__ __half g_Xh[(size_t)MROWS*CC];      /* X fp16 */
__device__ __half g_Ah[(size_t)MROWS*CC];      /* attn out fp16 */
__device__ __half g_Wqc[(size_t)C3*CC];        /* Wqkv fp16 */
__device__ __half g_Wpc[(size_t)CC*CC];        /* Wproj permuted fp16 */

/* ---------------- PTX helpers --------------------------------------------- */
__device__ __forceinline__ uint32_t smem_u32(const void* p) {
    uint32_t a;
    asm("{ .reg .u64 t; cvta.to.shared.u64 t, %1; cvt.u32.u64 %0, t; }" : "=r"(a) : "l"(p));
    return a;
}
__device__ __forceinline__ void cpasync16(uint32_t s, const void* g) {
    asm volatile("cp.async.cg.shared.global [%0], [%1], 16;" :: "r"(s), "l"(g));
}
#define CP_COMMIT() asm volatile("cp.async.commit_group;" ::: "memory")
#define CP_WAIT1()  asm volatile("cp.async.wait_group 1;" ::: "memory")
#define CP_WAIT0()  asm volatile("cp.async.wait_group 0;" ::: "memory")

__device__ __forceinline__ void ldsm_x4(uint32_t* r, uint32_t addr) {
    asm volatile("ldmatrix.sync.aligned.m8n8.x4.shared.b16 {%0,%1,%2,%3}, [%4];"
                 : "=r"(r[0]), "=r"(r[1]), "=r"(r[2]), "=r"(r[3]) : "r"(addr));
}
__device__ __forceinline__ void ldsm_x4_t(uint32_t* r, uint32_t addr) {
    asm volatile("ldmatrix.sync.aligned.m8n8.x4.trans.shared.b16 {%0,%1,%2,%3}, [%4];"
                 : "=r"(r[0]), "=r"(r[1]), "=r"(r[2]), "=r"(r[3]) : "r"(addr));
}
__device__ __forceinline__ void mma16816(float* c, const uint32_t* a, const uint32_t* b) {
    asm volatile("mma.sync.aligned.m16n8k16.row.col.f32.f16.f16.f32 "
                 "{%0,%1,%2,%3}, {%4,%5,%6,%7}, {%8,%9}, {%0,%1,%2,%3};"
                 : "+f"(c[0]), "+f"(c[1]), "+f"(c[2]), "+f"(c[3])
                 : "r"(a[0]), "r"(a[1]), "r"(a[2]), "r"(a[3]), "r"(b[0]), "r"(b[1]));
}
__device__ __forceinline__ uint32_t pk2h(__half a, __half b) {
    __half2 t; t.x = a; t.y = b;
    return *(uint32_t*)&t;
}

/* ---------------- merged conversions --------------------------------------- */
__global__ __launch_bounds__(256) void conv_all(const float* __restrict__ x,
                                                const float* __restrict__ Wq,
                                                const float* __restrict__ Wp) {
    int b = blockIdx.x;
    if (b < NBLK_A) {
        int t = b * 256 + threadIdx.x;
        float4 v = *(const float4*)(x + (size_t)t * 4);
        uint2 uh;
        uh.x = pk2h(__float2half_rn(v.x), __float2half_rn(v.y));
        uh.y = pk2h(__float2half_rn(v.z), __float2half_rn(v.w));
        *(uint2*)(g_Xh + (size_t)t * 4) = uh;
    } else if (b < NBLK_A + NBLK_WQ) {
        int t = (b - NBLK_A) * 256 + threadIdx.x;
        float4 v = *(const float4*)(Wq + (size_t)t * 4);
        uint2 uh;
        uh.x = pk2h(__float2half_rn(v.x), __float2half_rn(v.y));
        uh.y = pk2h(__float2half_rn(v.z), __float2half_rn(v.w));
        *(uint2*)(g_Wqc + (size_t)t * 4) = uh;
    } else {
        int t = (b - NBLK_A - NBLK_WQ) * 256 + threadIdx.x;
        int o = t / CC, c = t - o * CC;
        int h = c >> 6, d = c & 63;
        g_Wpc[(size_t)o * CC + c] = __float2half_rn(Wp[(size_t)o * CC + d * HH + h]);
    }
}

/* ---------------- mma.sync GEMM mainloop ------------------------------------ */
/* CTA 128x128, 4 warps (2x2), warp tile 64x64. fp16, BK=64, 2-stage, K=384.  */
__device__ __forceinline__ void prefetch_kt(const __half* Ab, const __half* Bb,
                                            uint32_t sm, int kt, int tid) {
    const int st = kt & 1;
    const int k0 = kt * 64;
    const uint32_t sa = sm + st * STAGE_BYTES;
    const uint32_t sb = sm + B_REGION + st * STAGE_BYTES;
    #pragma unroll
    for (int it = 0; it < 8; it++) {
        int idx = it * 128 + tid;
        int r = idx >> 3, jj = idx & 7;
        cpasync16(sa + r * STRB + jj * 16, Ab + (size_t)r * CC + k0 + jj * 8);
        cpasync16(sb + r * STRB + jj * 16, Bb + (size_t)r * CC + k0 + jj * 8);
    }
}
__device__ __forceinline__ void gemm_mainloop(const __half* __restrict__ A,
                                              const __half* __restrict__ Bm,
                                              int rowBase, int colBase,
                                              uint32_t sm, float acc[4][8][4]) {
    const int tid  = threadIdx.x;
    const int wid  = tid >> 5, lane = tid & 31;
    const int wr   = wid >> 1, wc = wid & 1;

    #pragma unroll
    for (int i = 0; i < 4; i++)
        #pragma unroll
        for (int j = 0; j < 8; j++)
            #pragma unroll
            for (int k = 0; k < 4; k++) acc[i][j][k] = 0.f;

    const __half* Ab = A + (size_t)rowBase * CC;
    const __half* Bb = Bm + (size_t)colBase * CC;

    prefetch_kt(Ab, Bb, sm, 0, tid); CP_COMMIT();

    const uint32_t aoff = (uint32_t)((wr * 64 + (lane & 15)) * STRB + ((lane >> 4) & 1) * 16);
    const uint32_t boff = (uint32_t)((wc * 64 + (lane & 7) + ((lane >> 4) & 1) * 8) * STRB
                                     + ((lane >> 3) & 1) * 16);

    #pragma unroll 1
    for (int kt = 0; kt < NKT; kt++) {
        if (kt + 1 < NKT) { prefetch_kt(Ab, Bb, sm, kt + 1, tid); }
        CP_COMMIT();
        CP_WAIT1();
        __syncthreads();

        const int st = kt & 1;
        const uint32_t aBase = sm + st * STAGE_BYTES + aoff;
        const uint32_t bBase = sm + B_REGION + st * STAGE_BYTES + boff;
        #pragma unroll
        for (int ks = 0; ks < 4; ks++) {
            uint32_t af[4][4], bf[4][4];
            #pragma unroll
            for (int jj = 0; jj < 4; jj++)
                ldsm_x4(bf[jj], bBase + (uint32_t)(jj * 16 * STRB + ks * 32));
            #pragma unroll
            for (int i = 0; i < 4; i++)
                ldsm_x4(af[i], aBase + (uint32_t)(i * 16 * STRB + ks * 32));
            #pragma unroll
            for (int i = 0; i < 4; i++)
                #pragma unroll
                for (int jj = 0; jj < 4; jj++) {
                    mma16816(acc[i][2 * jj],     af[i], bf[jj]);
                    mma16816(acc[i][2 * jj + 1], af[i], bf[jj] + 2);
                }
        }
        __syncthreads();
    }
    CP_WAIT0();
}

/* ---------------- QKV GEMM kernel (direct-STG epilogue) -------------------- */
__global__ __launch_bounds__(128, 3) void qkv_mma(const float* __restrict__ bias) {
    extern __shared__ char dynsm[];
    uint32_t sm = smem_u32(dynsm);
    const int colBase = blockIdx.x * 128;
    const int rowBase = blockIdx.y * 128;
    const int s = colBase / CC;

    float acc[4][8][4];
    gemm_mainloop(g_Xh, g_Wqc, rowBase, colBase, sm, acc);

    const int tid = threadIdx.x, wid = tid >> 5, lane = tid & 31;
    const int wr = wid >> 1, wc = wid & 1;
    const int rl = lane >> 2, cl = 2 * (lane & 3);
    const int hb = (colBase - s * CC) >> 6;
    const float mul = (s == 0) ? QK_SCALE : 1.0f;
    __half* dst = (s == 0) ? g_Qh : (s == 1) ? g_Kh : g_Vh;

    #pragma unroll
    for (int i = 0; i < 4; i++) {
        int m0 = rowBase + wr * 64 + i * 16 + rl;
        int m1 = m0 + 8;
        int bt0 = m0 / NP, n0 = m0 - bt0 * NP;
        int bt1 = m1 / NP, n1 = m1 - bt1 * NP;
        #pragma unroll
        for (int j = 0; j < 8; j++) {
            int c = wc * 64 + j * 8 + cl;
            int hh = c >> 6, d = c & 63;
            float2 bj = *(const float2*)(bias + colBase + c);
            float v0 = (acc[i][j][0] + bj.x) * mul;
            float v1 = (acc[i][j][1] + bj.y) * mul;
            float v2 = (acc[i][j][2] + bj.x) * mul;
            float v3 = (acc[i][j][3] + bj.y) * mul;
            size_t o0 = ((size_t)(bt0 * HH + hb + hh) * NP + n0) * HD + d;
            size_t o1 = ((size_t)(bt1 * HH + hb + hh) * NP + n1) * HD + d;
            *(uint32_t*)(dst + o0) = pk2h(__float2half_rn(v0), __float2half_rn(v1));
            *(uint32_t*)(dst + o1) = pk2h(__float2half_rn(v2), __float2half_rn(v3));
        }
    }
}

/* ---------------- proj GEMM kernel (direct-STG epilogue) ------------------- */
__global__ __launch_bounds__(128, 3) void proj_mma(const float* __restrict__ bias,
                                                   float* __restrict__ out) {
    extern __shared__ char dynsm[];
    uint32_t sm = smem_u32(dynsm);
    const int colBase = blockIdx.x * 128;
    const int rowBase = blockIdx.y * 128;

    float acc[4][8][4];
    gemm_mainloop(g_Ah, g_Wpc, rowBase, colBase, sm, acc);

    const int tid = threadIdx.x, wid = tid >> 5, lane = tid & 31;
    const int wr = wid >> 1, wc = wid & 1;
    const int rl = lane >> 2, cl = 2 * (lane & 3);

    #pragma unroll
    for (int i = 0; i < 4; i++) {
        int m0 = rowBase + wr * 64 + i * 16 + rl;
        int m1 = m0 + 8;
        #pragma unroll
        for (int j = 0; j < 8; j++) {
            int col = colBase + wc * 64 + j * 8 + cl;
            float2 bj = *(const float2*)(bias + col);
            float2 v0; v0.x = acc[i][j][0] + bj.x; v0.y = acc[i][j][1] + bj.y;
            float2 v1; v1.x = acc[i][j][2] + bj.x; v1.y = acc[i][j][3] + bj.y;
            *(float2*)(out + (size_t)m0 * CC + col) = v0;
            *(float2*)(out + (size_t)m1 * CC + col) = v1;
        }
    }
}

/* ---------------- attention via mma.sync (pure fp16, row-split CTAs) ------- */
/* 2 CTAs per (bt,h): each 7 warps x 16 rows = 112 query rows. 2 CTAs/SM.     */
template<int NT>
__device__ __forceinline__ void attn_chunk(uint32_t sb, int lane, int cbase,
                                           const uint32_t qh[4][4],
                                           float o[8][4], float& lp0, float& lp1) {
    float s[NT][4];
    #pragma unroll
    for (int t = 0; t < NT; t++)
        #pragma unroll
        for (int e = 0; e < 4; e++) s[t][e] = 0.f;

    /* --- QK: x4 loads two n-tiles --- */
    #pragma unroll
    for (int tp = 0; tp < NT / 2; tp++) {
        #pragma unroll
        for (int ks = 0; ks < 4; ks++) {
            uint32_t r[4];
            uint32_t off = (uint32_t)((cbase + tp * 16 + (lane & 15)) * KSTRB
                                      + ks * 32 + ((lane >> 4) & 1) * 16);
            ldsm_x4(r, sb + SM_KH + off);
            uint32_t b0[2] = { r[0], r[2] };
            uint32_t b1[2] = { r[1], r[3] };
            mma16816(s[2 * tp],     qh[ks], b0);
            mma16816(s[2 * tp + 1], qh[ks], b1);
        }
    }

    /* --- exp + mask + pack P --- */
    uint32_t phi[NT/2][4];
    #pragma unroll
    for (int t = 0; t < NT; t++) {
        int c0 = cbase + t * 8 + 2 * (lane & 3);
        float p0 = (c0     < NP) ? __expf(s[t][0]) : 0.f;
        float p1 = (c0 + 1 < NP) ? __expf(s[t][1]) : 0.f;
        float p2 = (c0     < NP) ? __expf(s[t][2]) : 0.f;
        float p3 = (c0 + 1 < NP) ? __expf(s[t][3]) : 0.f;
        lp0 += p0 + p1;
        lp1 += p2 + p3;
        int j = t >> 1, oreg = (t & 1) * 2;
        phi[j][oreg]     = pk2h(__float2half_rn(p0), __float2half_rn(p1));
        phi[j][oreg + 1] = pk2h(__float2half_rn(p2), __float2half_rn(p3));
    }

    /* --- PV: x4.trans loads two nd-groups --- */
    #pragma unroll
    for (int j = 0; j < NT / 2; j++) {
        #pragma unroll
        for (int np = 0; np < 4; np++) {
            uint32_t r[4];
            uint32_t off = (uint32_t)((cbase + j * 16 + (lane & 15)) * KSTRB
                                      + np * 32 + ((lane >> 4) & 1) * 16);
            ldsm_x4_t(r, sb + SM_VH + off);
            mma16816(o[2 * np],     phi[j], r);
            mma16816(o[2 * np + 1], phi[j], r + 2);
        }
    }
}

__global__ __launch_bounds__(224, 2) void attn_mma() {
    extern __shared__ char smc[];
    uint32_t sb = smem_u32(smc);
    const int bx = blockIdx.x;
    const int bh = bx >> 1, half = bx & 1;     /* bh = bt*6 + h */
    const int tid = threadIdx.x, wid = tid >> 5, lane = tid & 31;

    const size_t base = (size_t)bh * NP * HD;
    /* K/V copy-in via cp.async (both halves read same data; 2nd hits L2) */
    for (int i = tid; i < NP * 8; i += 224) {
        int r = i >> 3, j = i & 7;
        uint32_t doff = (uint32_t)(r * KSTRB + j * 16);
        cpasync16(sb + SM_KH + doff, (const uint4*)(g_Kh + base) + i);
        cpasync16(sb + SM_VH + doff, (const uint4*)(g_Vh + base) + i);
    }
    CP_COMMIT();
    /* zero V pad rows 196-207 (NaN x 0 guard in PV) */
    if (tid < 108)
        *(uint4*)(smc + SM_VH + 196 * KSTRB + tid * 16) = make_uint4(0, 0, 0, 0);

    /* Q fragments straight from gmem (row-clamped) */
    uint32_t qh[4][4];
    {
        const uint32_t* qhp = (const uint32_t*)(g_Qh + base);
        int r  = half * 112 + wid * 16 + (lane >> 2);
        int r2 = r + 8;
        int ra  = (r  < NP) ? r  : NP - 1;
        int r2a = (r2 < NP) ? r2 : NP - 1;
        int c = lane & 3;
        #pragma unroll
        for (int ks = 0; ks < 4; ks++) {
            qh[ks][0] = qhp[ra  * 32 + ks * 8 + c];
            qh[ks][1] = qhp[r2a * 32 + ks * 8 + c];
            qh[ks][2] = qhp[ra  * 32 + ks * 8 + 4 + c];
            qh[ks][3] = qhp[r2a * 32 + ks * 8 + 4 + c];
        }
    }
    CP_WAIT0();
    __syncthreads();

    float o[8][4];
    #pragma unroll
    for (int nd = 0; nd < 8; nd++)
        #pragma unroll
        for (int e = 0; e < 4; e++) o[nd][e] = 0.f;
    float lp0 = 0.f, lp1 = 0.f;

    attn_chunk<14>(sb, lane, 0,   qh, o, lp0, lp1);
    attn_chunk<12>(sb, lane, 112, qh, o, lp0, lp1);

    lp0 += __shfl_xor_sync(0xFFFFFFFFu, lp0, 1);
    lp0 += __shfl_xor_sync(0xFFFFFFFFu, lp0, 2);
    lp1 += __shfl_xor_sync(0xFFFFFFFFu, lp1, 1);
    lp1 += __shfl_xor_sync(0xFFFFFFFFu, lp1, 2);
    const float inv0 = 1.0f / lp0, inv1 = 1.0f / lp1;

    const int bt = bh / HH, h = bh - bt * HH;
    const int r0 = half * 112 + wid * 16 + (lane >> 2);
    const int cl = 2 * (lane & 3);
    #pragma unroll
    for (int nd = 0; nd < 8; nd++) {
        int col = h * HD + nd * 8 + cl;
        if (r0 < NP) {
            size_t ro = ((size_t)bt * NP + r0) * CC + col;
            *(uint32_t*)(g_Ah + ro) = pk2h(__float2half_rn(o[nd][0] * inv0),
                                           __float2half_rn(o[nd][1] * inv0));
        }
        if (r0 + 8 < NP) {
            size_t ro = ((size_t)bt * NP + r0 + 8) * CC + col;
            *(uint32_t*)(g_Ah + ro) = pk2h(__float2half_rn(o[nd][2] * inv1),
                                           __float2half_rn(o[nd][3] * inv1));
        }
    }
}

/* ---------------- launch --------------------------------------------------- */
extern "C" void kernel_launch(void* const* d_in, const int* in_sizes, int n_in,
                              void* d_out, int out_size) {
    const float* x     = (const float*)d_in[0];
    const float* Wqkv  = (const float*)d_in[1];
    const float* bqkv  = (const float*)d_in[2];
    const float* Wproj = (const float*)d_in[3];
    const float* bproj = (const float*)d_in[4];
    float* out = (float*)d_out;

    cudaFuncSetAttribute(attn_mma, cudaFuncAttributeMaxDynamicSharedMemorySize, ATT_SMEM);
    cudaFuncSetAttribute(qkv_mma,  cudaFuncAttributeMaxDynamicSharedMemorySize, SMEM_SZ);
    cudaFuncSetAttribute(proj_mma, cudaFuncAttributeMaxDynamicSharedMemorySize, SMEM_SZ);

    conv_all<<<NBLK_A + NBLK_WQ + NBLK_WP, 256>>>(x, Wqkv, Wproj);
    qkv_mma<<<dim3(C3 / 128, MROWS / 128), 128, SMEM_SZ>>>(bqkv);
    attn_mma<<<NBH * 2, 224, ATT_SMEM>>>();
    proj_mma<<<dim3(CC / 128, MROWS / 128), 128, SMEM_SZ>>>(bproj, out);
}